// round 3
// baseline (speedup 1.0000x reference)
#include <cuda_runtime.h>
#include <stdint.h>

// NeighborNoiser, partitionable-threefry weights (verified bit-exact in R2).
// R3: pipe rebalance — half the hash rounds do the rotate as IMAD.WIDE.U32
// (fma pipe) + single fused LOP3 ((lo|hi)^x0), instead of SHF+LOP3 (both alu).

#define N1 25165824u                    // 8*3*1024*1024

// ---- round variants ------------------------------------------------------
__device__ __forceinline__ void r_shf(uint32_t& x0, uint32_t& x1, const int d) {
    x0 += x1;
    x1 = __funnelshift_l(x1, x1, d) ^ x0;   // SHF (alu) + LOP3 (alu)
}

__device__ __forceinline__ void r_wide(uint32_t& x0, uint32_t& x1, uint32_t pw) {
    x0 += x1;
    uint32_t lo, hi;
    // rotl(x1,d) as the two halves of x1 * 2^d — IMAD.WIDE.U32 on the fma pipe.
    asm("{\n\t"
        ".reg .b64 w;\n\t"
        "mul.wide.u32 w, %2, %3;\n\t"
        "mov.b64 {%0, %1}, w;\n\t"
        "}" : "=r"(lo), "=r"(hi) : "r"(x1), "r"(pw));
    x1 = (lo | hi) ^ x0;                    // single LOP3, lut 0x56
}

// ---- threefry2x32, key (0,42), counter (0,ctr), output fold x0^x1 --------
template<bool WIDE>
__device__ __forceinline__ uint32_t tf_bits(uint32_t ctr) {
    const uint32_t ks1 = 42u;
    const uint32_t ks2 = 0x1BD11BDAu ^ 42u;     // ks0 = 0

    uint32_t x0 = 0u;                           // 0 + ks0
    uint32_t x1 = ctr + ks1;

    if (WIDE) {
        const uint32_t p13 = 1u << 13, p15 = 1u << 15, p26 = 1u << 26, p6  = 1u << 6;
        const uint32_t p17 = 1u << 17, p29 = 1u << 29, p16 = 1u << 16, p24 = 1u << 24;
        r_wide(x0,x1,p13); r_wide(x0,x1,p15); r_wide(x0,x1,p26); r_wide(x0,x1,p6);
        x0 += ks1; x1 += ks2 + 1u;
        r_wide(x0,x1,p17); r_wide(x0,x1,p29); r_wide(x0,x1,p16); r_wide(x0,x1,p24);
        x0 += ks2; x1 += 2u;                    // ks0 + 2
        r_wide(x0,x1,p13); r_wide(x0,x1,p15); r_wide(x0,x1,p26); r_wide(x0,x1,p6);
        /* x0 += ks0 (0) */ x1 += ks1 + 3u;
        r_wide(x0,x1,p17); r_wide(x0,x1,p29); r_wide(x0,x1,p16); r_wide(x0,x1,p24);
        x0 += ks1; x1 += ks2 + 4u;
        r_wide(x0,x1,p13); r_wide(x0,x1,p15); r_wide(x0,x1,p26); r_wide(x0,x1,p6);
        x0 += ks2; x1 += 5u;                    // ks0 + 5
    } else {
        r_shf(x0,x1,13); r_shf(x0,x1,15); r_shf(x0,x1,26); r_shf(x0,x1,6);
        x0 += ks1; x1 += ks2 + 1u;
        r_shf(x0,x1,17); r_shf(x0,x1,29); r_shf(x0,x1,16); r_shf(x0,x1,24);
        x0 += ks2; x1 += 2u;
        r_shf(x0,x1,13); r_shf(x0,x1,15); r_shf(x0,x1,26); r_shf(x0,x1,6);
        x1 += ks1 + 3u;
        r_shf(x0,x1,17); r_shf(x0,x1,29); r_shf(x0,x1,16); r_shf(x0,x1,24);
        x0 += ks1; x1 += ks2 + 4u;
        r_shf(x0,x1,13); r_shf(x0,x1,15); r_shf(x0,x1,26); r_shf(x0,x1,6);
        x0 += ks2; x1 += 5u;
    }
    return x0 ^ x1;
}

// bits>>9 done as IMAD.HI (fma pipe); OR of disjoint bits done as add (flexible)
__device__ __forceinline__ float u01(uint32_t bits) {
    return __uint_as_float(__umulhi(bits, 1u << 23) + 0x3f800000u) - 1.0f;
}

__global__ __launch_bounds__(256)
void neighbor_noiser_kernel(const float* __restrict__ t, float* __restrict__ out) {
    uint32_t j = blockIdx.x * blockDim.x + threadIdx.x;   // linear idx in (24,1024,1024)

    uint32_t plane = j >> 20;
    uint32_t pos   = j & 0xFFFFFu;
    uint32_t y     = pos >> 10;
    uint32_t x     = pos & 1023u;

    const float* p = t + ((size_t)plane << 20);
    uint32_t yu = (y == 0u)    ? 0u    : y - 1u;
    uint32_t yd = (y == 1023u) ? 1023u : y + 1u;
    uint32_t xl = (x == 0u)    ? 0u    : x - 1u;
    uint32_t xr = (x == 1023u) ? 1023u : x + 1u;

    float up = __ldg(p + (yu << 10) + x);
    float dn = __ldg(p + (yd << 10) + x);
    float lf = __ldg(p + (y  << 10) + xl);
    float rt = __ldg(p + (y  << 10) + xr);

    // 4 independent chains: 2 on the wide-mul rotate (fma), 2 on SHF (alu)
    uint32_t bu = tf_bits<true >(j);
    uint32_t bd = tf_bits<true >(j + N1);
    uint32_t bl = tf_bits<false>(j + 2u * N1);
    uint32_t br = tf_bits<false>(j + 3u * N1);

    float ur = u01(bu);
    float dr = u01(bd);
    float lr = u01(bl);
    float rr = u01(br);

    float s   = (ur + dr) + (lr + rr);
    float num = fmaf(up, ur, fmaf(dn, dr, fmaf(lf, lr, rt * rr)));
    out[j] = __fdividef(num, s);
}

extern "C" void kernel_launch(void* const* d_in, const int* in_sizes, int n_in,
                              void* d_out, int out_size) {
    const float* t = (const float*)d_in[0];
    float* out = (float*)d_out;
    (void)in_sizes; (void)n_in; (void)out_size;

    const uint32_t threads = 256;
    const uint32_t blocks = N1 / threads;    // 98304, exact
    neighbor_noiser_kernel<<<blocks, threads>>>(t, out);
}

// round 4
// speedup vs baseline: 1.0893x; 1.0893x over previous
#include <cuda_runtime.h>
#include <stdint.h>

// NeighborNoiser — partitionable threefry2x32, key (0,42), fold = x0^x1.
// R4: 2 pixels/thread (8 independent hash chains for ILP), 1 wide-mul chain +
// 3 SHF chains per pixel (alu/fma balance point), umulhi-based u01.

#define N1 25165824u                    // 8*3*1024*1024

__device__ __forceinline__ void r_shf(uint32_t& x0, uint32_t& x1, const int d) {
    x0 += x1;
    x1 = __funnelshift_l(x1, x1, d) ^ x0;       // SHF(alu) + LOP3(alu)
}

__device__ __forceinline__ void r_wide(uint32_t& x0, uint32_t& x1, uint32_t pw) {
    x0 += x1;
    uint32_t lo, hi;
    asm("{\n\t"
        ".reg .b64 w;\n\t"
        "mul.wide.u32 w, %2, %3;\n\t"
        "mov.b64 {%0, %1}, w;\n\t"
        "}" : "=r"(lo), "=r"(hi) : "r"(x1), "r"(pw));
    x1 = (lo | hi) ^ x0;                        // IMAD.WIDE(fma) + LOP3(alu)
}

template<bool WIDE>
__device__ __forceinline__ uint32_t tf_bits(uint32_t ctr) {
    const uint32_t ks1 = 42u;
    const uint32_t ks2 = 0x1BD11BDAu ^ 42u;

    uint32_t x1 = ctr + ks1;
    uint32_t x0 = x1;                           // round-1 add with x0 = 0

    if (WIDE) {
        const uint32_t p13 = 1u<<13, p15 = 1u<<15, p26 = 1u<<26, p6 = 1u<<6;
        const uint32_t p17 = 1u<<17, p29 = 1u<<29, p16 = 1u<<16, p24 = 1u<<24;
        { uint32_t lo, hi;                      // round 1 (x0 already = x1)
          asm("{\n\t.reg .b64 w;\n\tmul.wide.u32 w, %2, %3;\n\tmov.b64 {%0, %1}, w;\n\t}"
              : "=r"(lo), "=r"(hi) : "r"(x1), "r"(p13));
          x1 = (lo | hi) ^ x0; }
        r_wide(x0,x1,p15); r_wide(x0,x1,p26); r_wide(x0,x1,p6);
        x0 += ks1; x1 += ks2 + 1u;
        r_wide(x0,x1,p17); r_wide(x0,x1,p29); r_wide(x0,x1,p16); r_wide(x0,x1,p24);
        x0 += ks2; x1 += 2u;
        r_wide(x0,x1,p13); r_wide(x0,x1,p15); r_wide(x0,x1,p26); r_wide(x0,x1,p6);
        x1 += ks1 + 3u;
        r_wide(x0,x1,p17); r_wide(x0,x1,p29); r_wide(x0,x1,p16); r_wide(x0,x1,p24);
        x0 += ks1; x1 += ks2 + 4u;
        r_wide(x0,x1,p13); r_wide(x0,x1,p15); r_wide(x0,x1,p26); r_wide(x0,x1,p6);
        x0 += ks2; x1 += 5u;
    } else {
        x1 = __funnelshift_l(x1, x1, 13) ^ x0;  // round 1
        r_shf(x0,x1,15); r_shf(x0,x1,26); r_shf(x0,x1,6);
        x0 += ks1; x1 += ks2 + 1u;
        r_shf(x0,x1,17); r_shf(x0,x1,29); r_shf(x0,x1,16); r_shf(x0,x1,24);
        x0 += ks2; x1 += 2u;
        r_shf(x0,x1,13); r_shf(x0,x1,15); r_shf(x0,x1,26); r_shf(x0,x1,6);
        x1 += ks1 + 3u;
        r_shf(x0,x1,17); r_shf(x0,x1,29); r_shf(x0,x1,16); r_shf(x0,x1,24);
        x0 += ks1; x1 += ks2 + 4u;
        r_shf(x0,x1,13); r_shf(x0,x1,15); r_shf(x0,x1,26); r_shf(x0,x1,6);
        x0 += ks2; x1 += 5u;
    }
    return x0 ^ x1;
}

// bits>>9 as IMAD.HI (fma); OR of disjoint fields as IADD (flexible)
__device__ __forceinline__ float u01(uint32_t bits) {
    return __uint_as_float(__umulhi(bits, 1u << 23) + 0x3f800000u) - 1.0f;
}

__global__ __launch_bounds__(256)
void neighbor_noiser_kernel(const float* __restrict__ t, float* __restrict__ out) {
    uint32_t gid  = blockIdx.x * blockDim.x + threadIdx.x;
    uint32_t base = gid * 2u;                   // 2 adjacent pixels in one row

    uint32_t plane = base >> 20;
    uint32_t pos   = base & 0xFFFFFu;
    uint32_t y     = pos >> 10;
    uint32_t x     = pos & 1023u;               // even

    const float* p = t + ((size_t)plane << 20);
    uint32_t yu = (y == 0u)    ? 0u    : y - 1u;
    uint32_t yd = (y == 1023u) ? 1023u : y + 1u;

    const float* rowc = p + (y  << 10);
    float2 up = __ldg((const float2*)(p + (yu << 10) + x));
    float2 dn = __ldg((const float2*)(p + (yd << 10) + x));
    float2 ct = __ldg((const float2*)(rowc + x));
    float lf_e = (x == 0u)     ? ct.x : __ldg(rowc + x - 1u);
    float rt_e = (x == 1022u)  ? ct.y : __ldg(rowc + x + 2u);

    // 8 independent hash chains; per pixel: up-chain wide, other 3 SHF.
    uint32_t j0 = base, j1 = base + 1u;
    uint32_t bu0 = tf_bits<true >(j0);
    uint32_t bu1 = tf_bits<true >(j1);
    uint32_t bd0 = tf_bits<false>(j0 + N1);
    uint32_t bd1 = tf_bits<false>(j1 + N1);
    uint32_t bl0 = tf_bits<false>(j0 + 2u * N1);
    uint32_t bl1 = tf_bits<false>(j1 + 2u * N1);
    uint32_t br0 = tf_bits<false>(j0 + 3u * N1);
    uint32_t br1 = tf_bits<false>(j1 + 3u * N1);

    float ur0 = u01(bu0), dr0 = u01(bd0), lr0 = u01(bl0), rr0 = u01(br0);
    float ur1 = u01(bu1), dr1 = u01(bd1), lr1 = u01(bl1), rr1 = u01(br1);

    float s0   = (ur0 + dr0) + (lr0 + rr0);
    float num0 = fmaf(up.x, ur0, fmaf(dn.x, dr0, fmaf(lf_e, lr0, ct.y * rr0)));
    float s1   = (ur1 + dr1) + (lr1 + rr1);
    float num1 = fmaf(up.y, ur1, fmaf(dn.y, dr1, fmaf(ct.x, lr1, rt_e * rr1)));

    float2 o = make_float2(__fdividef(num0, s0), __fdividef(num1, s1));
    *reinterpret_cast<float2*>(out + base) = o;
}

extern "C" void kernel_launch(void* const* d_in, const int* in_sizes, int n_in,
                              void* d_out, int out_size) {
    const float* t = (const float*)d_in[0];
    float* out = (float*)d_out;
    (void)in_sizes; (void)n_in; (void)out_size;

    const uint32_t threads = 256;
    const uint32_t blocks = (N1 / 2u) / threads;   // 49152, exact
    neighbor_noiser_kernel<<<blocks, threads>>>(t, out);
}

// round 7
// speedup vs baseline: 1.1341x; 1.0412x over previous
#include <cuda_runtime.h>
#include <stdint.h>

// NeighborNoiser — partitionable threefry2x32, key (0,42), fold = x0^x1 (bit-exact, R2+).
// R6 = R5 re-bench (R5 hit a container-infra failure, no measurement taken):
// 4 px/thread (16 chains), 64-reg budget via __launch_bounds__(256,4),
// IADD3-fused key schedule, float4 I/O. Pipe mix: 1 wide chain : 3 SHF per pixel.

#define N1 25165824u                    // 8*3*1024*1024

__device__ __forceinline__ uint32_t rotl(uint32_t v, const int d) {
    return __funnelshift_l(v, v, d);
}

#define RS(d) { x0 += x1; x1 = rotl(x1,(d)) ^ x0; }

// SHF-rotate chain
__device__ __forceinline__ uint32_t tf_shf(uint32_t ctr) {
    const uint32_t ks1 = 42u, ks2 = 0x1BD11BDAu ^ 42u;
    uint32_t x1 = ctr + ks1;
    uint32_t x0 = x1;                               // round 1 add with x0 = 0
    x1 = rotl(x1,13) ^ x0;
    RS(15) RS(26) RS(6)
    x1 += ks2 + 1u;  x0 = x0 + x1 + ks1;  x1 = rotl(x1,17) ^ x0;   // IADD3 fuse
    RS(29) RS(16) RS(24)
    x1 += 2u;        x0 = x0 + x1 + ks2;  x1 = rotl(x1,13) ^ x0;
    RS(15) RS(26) RS(6)
    x1 += ks1 + 3u;  x0 = x0 + x1;        x1 = rotl(x1,17) ^ x0;   // ks0 = 0
    RS(29) RS(16) RS(24)
    x1 += ks2 + 4u;  x0 = x0 + x1 + ks1;  x1 = rotl(x1,13) ^ x0;
    RS(15) RS(26) RS(6)
    x1 += 5u;
    return (x0 + ks2) ^ x1;
}

// wide-mul rotate (IMAD.WIDE on fma pipe), same arithmetic
__device__ __forceinline__ uint32_t wrot(uint32_t v, uint32_t pw) {
    uint32_t lo, hi;
    asm("{\n\t.reg .b64 w;\n\tmul.wide.u32 w, %2, %3;\n\tmov.b64 {%0, %1}, w;\n\t}"
        : "=r"(lo), "=r"(hi) : "r"(v), "r"(pw));
    return lo | hi;   // folds into following LOP3 with the ^ below
}

#define RW(p) { x0 += x1; x1 = wrot(x1,(p)) ^ x0; }

__device__ __forceinline__ uint32_t tf_wide(uint32_t ctr) {
    const uint32_t ks1 = 42u, ks2 = 0x1BD11BDAu ^ 42u;
    const uint32_t p13 = 1u<<13, p15 = 1u<<15, p26 = 1u<<26, p6 = 1u<<6;
    const uint32_t p17 = 1u<<17, p29 = 1u<<29, p16 = 1u<<16, p24 = 1u<<24;
    uint32_t x1 = ctr + ks1;
    uint32_t x0 = x1;
    x1 = wrot(x1,p13) ^ x0;
    RW(p15) RW(p26) RW(p6)
    x1 += ks2 + 1u;  x0 = x0 + x1 + ks1;  x1 = wrot(x1,p17) ^ x0;
    RW(p29) RW(p16) RW(p24)
    x1 += 2u;        x0 = x0 + x1 + ks2;  x1 = wrot(x1,p13) ^ x0;
    RW(p15) RW(p26) RW(p6)
    x1 += ks1 + 3u;  x0 = x0 + x1;        x1 = wrot(x1,p17) ^ x0;
    RW(p29) RW(p16) RW(p24)
    x1 += ks2 + 4u;  x0 = x0 + x1 + ks1;  x1 = wrot(x1,p13) ^ x0;
    RW(p15) RW(p26) RW(p6)
    x1 += 5u;
    return (x0 + ks2) ^ x1;
}

// bits>>9 as IMAD.HI (fma pipe); exponent OR as plain add (pipe-flexible)
__device__ __forceinline__ float u01(uint32_t bits) {
    return __uint_as_float(__umulhi(bits, 1u << 23) + 0x3f800000u) - 1.0f;
}

__global__ __launch_bounds__(256, 4)
void neighbor_noiser_kernel(const float* __restrict__ t, float* __restrict__ out) {
    uint32_t gid  = blockIdx.x * blockDim.x + threadIdx.x;
    uint32_t base = gid * 4u;                   // 4 adjacent pixels in one row

    uint32_t plane = base >> 20;
    uint32_t pos   = base & 0xFFFFFu;
    uint32_t y     = pos >> 10;
    uint32_t x     = pos & 1023u;               // multiple of 4

    const float* p = t + ((size_t)plane << 20);
    uint32_t yu = (y == 0u)    ? 0u    : y - 1u;
    uint32_t yd = (y == 1023u) ? 1023u : y + 1u;
    const float* rowc = p + (y << 10);

    float4 up4 = __ldg((const float4*)(p + (yu << 10) + x));
    float4 dn4 = __ldg((const float4*)(p + (yd << 10) + x));
    float4 ct4 = __ldg((const float4*)(rowc + x));
    float lf_e = (x == 0u)     ? ct4.x : __ldg(rowc + x - 1u);
    float rt_e = (x == 1020u)  ? ct4.w : __ldg(rowc + x + 4u);

    // 16 independent hash chains: per pixel, up-chain wide, other 3 SHF.
    uint32_t bu0 = tf_wide(base);
    uint32_t bu1 = tf_wide(base + 1u);
    uint32_t bu2 = tf_wide(base + 2u);
    uint32_t bu3 = tf_wide(base + 3u);
    uint32_t bd0 = tf_shf(base + N1);
    uint32_t bd1 = tf_shf(base + N1 + 1u);
    uint32_t bd2 = tf_shf(base + N1 + 2u);
    uint32_t bd3 = tf_shf(base + N1 + 3u);
    uint32_t bl0 = tf_shf(base + 2u*N1);
    uint32_t bl1 = tf_shf(base + 2u*N1 + 1u);
    uint32_t bl2 = tf_shf(base + 2u*N1 + 2u);
    uint32_t bl3 = tf_shf(base + 2u*N1 + 3u);
    uint32_t br0 = tf_shf(base + 3u*N1);
    uint32_t br1 = tf_shf(base + 3u*N1 + 1u);
    uint32_t br2 = tf_shf(base + 3u*N1 + 2u);
    uint32_t br3 = tf_shf(base + 3u*N1 + 3u);

    float upv[4] = {up4.x, up4.y, up4.z, up4.w};
    float dnv[4] = {dn4.x, dn4.y, dn4.z, dn4.w};
    float lfv[4] = {lf_e,  ct4.x, ct4.y, ct4.z};
    float rtv[4] = {ct4.y, ct4.z, ct4.w, rt_e};
    uint32_t buv[4] = {bu0, bu1, bu2, bu3};
    uint32_t bdv[4] = {bd0, bd1, bd2, bd3};
    uint32_t blv[4] = {bl0, bl1, bl2, bl3};
    uint32_t brv[4] = {br0, br1, br2, br3};

    float res[4];
#pragma unroll
    for (int i = 0; i < 4; i++) {
        float ur = u01(buv[i]);
        float dr = u01(bdv[i]);
        float lr = u01(blv[i]);
        float rr = u01(brv[i]);
        float s   = (ur + dr) + (lr + rr);
        float num = fmaf(upv[i], ur, fmaf(dnv[i], dr, fmaf(lfv[i], lr, rtv[i] * rr)));
        res[i] = __fdividef(num, s);
    }

    *reinterpret_cast<float4*>(out + base) = make_float4(res[0], res[1], res[2], res[3]);
}

extern "C" void kernel_launch(void* const* d_in, const int* in_sizes, int n_in,
                              void* d_out, int out_size) {
    const float* t = (const float*)d_in[0];
    float* out = (float*)d_out;
    (void)in_sizes; (void)n_in; (void)out_size;

    const uint32_t threads = 256;
    const uint32_t blocks = (N1 / 4u) / threads;   // 24576, exact
    neighbor_noiser_kernel<<<blocks, threads>>>(t, out);
}